// round 7
// baseline (speedup 1.0000x reference)
#include <cuda_runtime.h>
#include <cuda_fp16.h>
#include <cstdint>

// ---------------- problem constants ----------------
#define BROWS 32768
#define DMODEL 2048
#define NEXP 4
#define DEXP 512

// ---------------- device scratch (allocation-free rule) ----------------
__device__ __half g_xn [(size_t)BROWS * DMODEL];
__device__ __half g_v  [(size_t)BROWS * DMODEL];
__device__ __half g_eo [(size_t)BROWS * DMODEL];
__device__ float  g_rt [(size_t)BROWS * NEXP];
__device__ __half g_qvt[(size_t)NEXP * DEXP * DEXP];   // qkv V-slice, [e][n][k]
__device__ __half g_pjt[(size_t)NEXP * DEXP * DEXP];   // proj,        [e][n][k]
__device__ __half g_owt[(size_t)DMODEL * DMODEL];      // out_w,       [n][k]

__device__ __forceinline__ uint32_t smem_u32(const void* p) {
    uint32_t a;
    asm("{ .reg .u64 t; cvta.to.shared.u64 t, %1; cvt.u32.u64 %0, t; }" : "=r"(a) : "l"(p));
    return a;
}

#define CP16(dst, src) \
    asm volatile("cp.async.cg.shared.global [%0], [%1], 16;\n" :: "r"(dst), "l"(src))

#define LDSM_X4(r0, r1, r2, r3, addr) \
    asm volatile("ldmatrix.sync.aligned.m8n8.x4.shared.b16 {%0,%1,%2,%3}, [%4];" \
        : "=r"(r0), "=r"(r1), "=r"(r2), "=r"(r3) : "r"(addr))

// ---------------------------------------------------------------------------
// Kernel 0: RMSNorm + router softmax; writes xn as fp16 (rn)
// ---------------------------------------------------------------------------
__global__ void __launch_bounds__(256)
rmsnorm_router_kernel(const float* __restrict__ x, const float* __restrict__ nw,
                      const float* __restrict__ rw, const float* __restrict__ rb,
                      __half* __restrict__ xn, float* __restrict__ routing)
{
    __shared__ float red[8];
    __shared__ float red4[8][4];
    __shared__ float s_rn;

    const int b = blockIdx.x;
    const int tid = threadIdx.x;
    const int lane = tid & 31, warp = tid >> 5;

    const float4* xr = reinterpret_cast<const float4*>(x + (size_t)b * DMODEL);
    float4 v0 = xr[tid];
    float4 v1 = xr[tid + 256];

    float ss = v0.x*v0.x + v0.y*v0.y + v0.z*v0.z + v0.w*v0.w
             + v1.x*v1.x + v1.y*v1.y + v1.z*v1.z + v1.w*v1.w;
    #pragma unroll
    for (int o = 16; o; o >>= 1) ss += __shfl_xor_sync(0xffffffffu, ss, o);
    if (lane == 0) red[warp] = ss;
    __syncthreads();
    if (tid == 0) {
        float t = 0.f;
        #pragma unroll
        for (int i = 0; i < 8; i++) t += red[i];
        s_rn = rsqrtf(t * (1.0f / DMODEL) + 1e-6f);
    }
    __syncthreads();
    const float rn = s_rn;

    const float4* nwr = reinterpret_cast<const float4*>(nw);
    float4 w0 = nwr[tid], w1 = nwr[tid + 256];
    float4 y0 = make_float4(v0.x*rn*w0.x, v0.y*rn*w0.y, v0.z*rn*w0.z, v0.w*rn*w0.w);
    float4 y1 = make_float4(v1.x*rn*w1.x, v1.y*rn*w1.y, v1.z*rn*w1.z, v1.w*rn*w1.w);

    __half2* xo = reinterpret_cast<__half2*>(xn + (size_t)b * DMODEL);
    xo[tid * 2]             = __floats2half2_rn(y0.x, y0.y);
    xo[tid * 2 + 1]         = __floats2half2_rn(y0.z, y0.w);
    xo[(tid + 256) * 2]     = __floats2half2_rn(y1.x, y1.y);
    xo[(tid + 256) * 2 + 1] = __floats2half2_rn(y1.z, y1.w);

    const float4* rwr = reinterpret_cast<const float4*>(rw);
    float a0 = 0.f, a1 = 0.f, a2 = 0.f, a3 = 0.f;
    const int d0 = tid * 4;
    const int d1 = (tid + 256) * 4;
    float ys[8] = {y0.x, y0.y, y0.z, y0.w, y1.x, y1.y, y1.z, y1.w};
    int   ds[8] = {d0, d0+1, d0+2, d0+3, d1, d1+1, d1+2, d1+3};
    #pragma unroll
    for (int i = 0; i < 8; i++) {
        float4 w = rwr[ds[i]];
        a0 += ys[i] * w.x; a1 += ys[i] * w.y; a2 += ys[i] * w.z; a3 += ys[i] * w.w;
    }
    #pragma unroll
    for (int o = 16; o; o >>= 1) {
        a0 += __shfl_xor_sync(0xffffffffu, a0, o);
        a1 += __shfl_xor_sync(0xffffffffu, a1, o);
        a2 += __shfl_xor_sync(0xffffffffu, a2, o);
        a3 += __shfl_xor_sync(0xffffffffu, a3, o);
    }
    if (lane == 0) { red4[warp][0]=a0; red4[warp][1]=a1; red4[warp][2]=a2; red4[warp][3]=a3; }
    __syncthreads();
    if (tid == 0) {
        float l[4];
        #pragma unroll
        for (int e = 0; e < 4; e++) {
            l[e] = rb[e];
            #pragma unroll
            for (int i = 0; i < 8; i++) l[e] += red4[i][e];
        }
        float m = fmaxf(fmaxf(l[0], l[1]), fmaxf(l[2], l[3]));
        float p[4], s = 0.f;
        #pragma unroll
        for (int e = 0; e < 4; e++) { p[e] = expf(l[e] - m); s += p[e]; }
        float inv = 1.0f / s;
        #pragma unroll
        for (int e = 0; e < 4; e++) routing[(size_t)b * 4 + e] = p[e] * inv;
    }
}

// ---------------------------------------------------------------------------
// Weight transpose + fp16 round: out[e][n][k] = half(in[e][k][col_off + n])
// ---------------------------------------------------------------------------
__global__ void __launch_bounds__(256)
transpose_h(const float* __restrict__ in, __half* __restrict__ out,
            int src_ld, int col_off, int Kdim,
            long long in_es, long long out_es)
{
    __shared__ float t[32][33];
    const int e = blockIdx.z;
    in  += (long long)e * in_es;
    out += (long long)e * out_es;
    const int k0 = blockIdx.x * 32, n0 = blockIdx.y * 32;
    const int txx = threadIdx.x % 32;
    const int tyy = threadIdx.x / 32;   // 0..7
    #pragma unroll
    for (int i = 0; i < 32; i += 8)
        t[tyy + i][txx] = in[(size_t)(k0 + tyy + i) * src_ld + col_off + n0 + txx];
    __syncthreads();
    #pragma unroll
    for (int i = 0; i < 32; i += 8)
        out[(size_t)(n0 + tyy + i) * Kdim + k0 + txx] = __float2half_rn(t[txx][tyy + i]);
}

// ---------------------------------------------------------------------------
// fp16 tensor-core GEMM: C[M,N] = A[M,K] @ Bt[N,K]^T
// BM=128, BN=256, BK=32, 5-stage cp.async (wait_group 3), 80B pitch,
// 512 threads = 16 warps as 2(M) x 8(N): warp tile 64x32. Single-buffer frags.
// MODE 0: C(half) = A@B
// MODE 1: C(half) = (A@B + bias) * routing
// MODE 2: C(float) = A@B + resid
// ---------------------------------------------------------------------------
static constexpr int G_BM = 128, G_BN = 256, G_BK = 32, G_STAGES = 5;
static constexpr int G_PITCH = 80;                          // bytes per smem row
static constexpr int G_ABYTES = G_BM * G_PITCH;             // 10240
static constexpr int G_BBYTES = G_BN * G_PITCH;             // 20480
static constexpr int G_STAGE  = G_ABYTES + G_BBYTES;        // 30720
static constexpr int G_SMEM   = G_STAGES * G_STAGE;         // 153600

template<int MODE>
__global__ void __launch_bounds__(512, 1)
gemm_h(const __half* __restrict__ A, int lda, int aColStep,
       const __half* __restrict__ Bt, int ldb, long long sB,
       void* __restrict__ Cv, int ldc, int cColStep,
       int K,
       const float* __restrict__ bias,
       const float* __restrict__ routing,
       const float* __restrict__ resid)
{
    extern __shared__ char smem[];
    const uint32_t sbase = smem_u32(smem);

    const int tid = threadIdx.x, lane = tid & 31, warp = tid >> 5;
    const int bn = blockIdx.x, bm = blockIdx.y, e = blockIdx.z;
    const int wm = warp & 1, wn = warp >> 1;        // 2 x 8
    const int m_base = wm * 64, n_base = wn * 32;

    const __half* Ag = A + (size_t)(bm * G_BM) * lda + e * aColStep;
    const __half* Bg = Bt + (long long)e * sB + (size_t)(bn * G_BN) * ldb;

    // cp.async layout: 512 threads, row = tid>>2 (0..127), chunk = tid&3 (16B)
    const int arow = tid >> 2, ac = tid & 3;

    auto load_stage = [&](int s, int kt) {
        const uint32_t as = sbase + s * G_STAGE;
        const uint32_t bs = as + G_ABYTES;
        const int k0 = kt * G_BK;
        CP16(as + (uint32_t)(arow * G_PITCH + ac * 16),
             Ag + (size_t)arow * lda + k0 + ac * 8);
        CP16(bs + (uint32_t)(arow * G_PITCH + ac * 16),
             Bg + (size_t)arow * ldb + k0 + ac * 8);
        CP16(bs + (uint32_t)((arow + 128) * G_PITCH + ac * 16),
             Bg + (size_t)(arow + 128) * ldb + k0 + ac * 8);
        asm volatile("cp.async.commit_group;\n" ::);
    };

    // ldmatrix per-thread address bases
    const int mt = lane >> 3, rr = lane & 7;
    const uint32_t aAddr0 = sbase +
        (uint32_t)((m_base + (mt & 1) * 8 + rr) * G_PITCH + (mt >> 1) * 16);
    const uint32_t bAddr0 = sbase + (uint32_t)G_ABYTES +
        (uint32_t)((n_base + (mt >> 1) * 8 + rr) * G_PITCH + (mt & 1) * 16);

    float acc[4][4][4];
    #pragma unroll
    for (int f = 0; f < 4; f++)
        #pragma unroll
        for (int g = 0; g < 4; g++)
            #pragma unroll
            for (int i = 0; i < 4; i++) acc[f][g][i] = 0.f;

    const int NT = K / G_BK;
    // prologue: 4 stages in flight
    load_stage(0, 0);
    load_stage(1, 1);
    load_stage(2, 2);
    load_stage(3, 3);

    for (int kt = 0; kt < NT; kt++) {
        asm volatile("cp.async.wait_group 3;\n" ::);
        __syncthreads();
        if (kt + 4 < NT) load_stage((kt + 4) % G_STAGES, kt + 4);

        const uint32_t so = (uint32_t)((kt % G_STAGES) * G_STAGE);

        #pragma unroll
        for (int ks = 0; ks < 2; ks++) {
            uint32_t a[4][4], b[2][4];
            const uint32_t ko = so + (uint32_t)(ks * 32);
            #pragma unroll
            for (int f = 0; f < 4; f++)
                LDSM_X4(a[f][0], a[f][1], a[f][2], a[f][3],
                        aAddr0 + ko + (uint32_t)(f * 16 * G_PITCH));
            #pragma unroll
            for (int gp = 0; gp < 2; gp++)
                LDSM_X4(b[gp][0], b[gp][1], b[gp][2], b[gp][3],
                        bAddr0 + ko + (uint32_t)(gp * 16 * G_PITCH));
            #pragma unroll
            for (int f = 0; f < 4; f++)
                #pragma unroll
                for (int g = 0; g < 4; g++) {
                    float* d = acc[f][g];
                    const uint32_t b0 = b[g >> 1][(g & 1) * 2];
                    const uint32_t b1 = b[g >> 1][(g & 1) * 2 + 1];
                    asm volatile(
                        "mma.sync.aligned.m16n8k16.row.col.f32.f16.f16.f32 "
                        "{%0,%1,%2,%3}, {%4,%5,%6,%7}, {%8,%9}, {%0,%1,%2,%3};\n"
                        : "+f"(d[0]), "+f"(d[1]), "+f"(d[2]), "+f"(d[3])
                        : "r"(a[f][0]), "r"(a[f][1]), "r"(a[f][2]), "r"(a[f][3]),
                          "r"(b0), "r"(b1));
                }
        }
    }

    // ---------------- epilogue ----------------
    const int gid = lane >> 2, tig = lane & 3;
    const int cColBase = e * cColStep + bn * G_BN;

    #pragma unroll
    for (int f = 0; f < 4; f++) {
        const size_t r0 = (size_t)bm * G_BM + m_base + f * 16 + gid;
        const size_t r1 = r0 + 8;
        float rt0 = 1.f, rt1 = 1.f;
        if (MODE == 1) {
            rt0 = routing[r0 * 4 + e];
            rt1 = routing[r1 * 4 + e];
        }
        #pragma unroll
        for (int g = 0; g < 4; g++) {
            const int ncl = n_base + g * 8 + tig * 2;   // col within block tile
            const int gc = cColBase + ncl;
            float v0 = acc[f][g][0], v1 = acc[f][g][1];
            float v2 = acc[f][g][2], v3 = acc[f][g][3];
            if (MODE == 1) {
                const float b0 = bias[e * DEXP + bn * G_BN + ncl];
                const float b1 = bias[e * DEXP + bn * G_BN + ncl + 1];
                v0 = (v0 + b0) * rt0; v1 = (v1 + b1) * rt0;
                v2 = (v2 + b0) * rt1; v3 = (v3 + b1) * rt1;
            }
            if (MODE == 2) {
                float* C = (float*)Cv;
                const float2 x0 = *reinterpret_cast<const float2*>(resid + r0 * ldc + gc);
                const float2 x1 = *reinterpret_cast<const float2*>(resid + r1 * ldc + gc);
                *reinterpret_cast<float2*>(C + r0 * ldc + gc) = make_float2(v0 + x0.x, v1 + x0.y);
                *reinterpret_cast<float2*>(C + r1 * ldc + gc) = make_float2(v2 + x1.x, v3 + x1.y);
            } else {
                __half* C = (__half*)Cv;
                *reinterpret_cast<__half2*>(C + r0 * ldc + gc) = __floats2half2_rn(v0, v1);
                *reinterpret_cast<__half2*>(C + r1 * ldc + gc) = __floats2half2_rn(v2, v3);
            }
        }
    }
}

// ---------------------------------------------------------------------------
extern "C" void kernel_launch(void* const* d_in, const int* in_sizes, int n_in,
                              void* d_out, int out_size)
{
    const float* x    = (const float*)d_in[0];
    const float* nw   = (const float*)d_in[1];
    const float* rw   = (const float*)d_in[2];
    const float* rb   = (const float*)d_in[3];
    const float* qkv  = (const float*)d_in[4];
    const float* proj = (const float*)d_in[5];
    const float* pb   = (const float*)d_in[6];
    const float* ow   = (const float*)d_in[7];
    float* out = (float*)d_out;

    __half *xn, *v, *eo, *qvt, *pjt, *owt;
    float *rt;
    cudaGetSymbolAddress((void**)&xn,  g_xn);
    cudaGetSymbolAddress((void**)&v,   g_v);
    cudaGetSymbolAddress((void**)&eo,  g_eo);
    cudaGetSymbolAddress((void**)&rt,  g_rt);
    cudaGetSymbolAddress((void**)&qvt, g_qvt);
    cudaGetSymbolAddress((void**)&pjt, g_pjt);
    cudaGetSymbolAddress((void**)&owt, g_owt);

    cudaFuncSetAttribute(gemm_h<0>, cudaFuncAttributeMaxDynamicSharedMemorySize, G_SMEM);
    cudaFuncSetAttribute(gemm_h<1>, cudaFuncAttributeMaxDynamicSharedMemorySize, G_SMEM);
    cudaFuncSetAttribute(gemm_h<2>, cudaFuncAttributeMaxDynamicSharedMemorySize, G_SMEM);

    // 1) RMSNorm + router (writes fp16 xn, fp32 routing)
    rmsnorm_router_kernel<<<BROWS, 256>>>(x, nw, rw, rb, xn, rt);

    // 2) weight transposes (+ fp16 round)
    transpose_h<<<dim3(16, 16, 4), 256>>>(qkv, qvt, 3 * DEXP, 2 * DEXP, DEXP,
                                          (long long)DEXP * 3 * DEXP, (long long)DEXP * DEXP);
    transpose_h<<<dim3(16, 16, 4), 256>>>(proj, pjt, DEXP, 0, DEXP,
                                          (long long)DEXP * DEXP, (long long)DEXP * DEXP);
    transpose_h<<<dim3(64, 64, 1), 256>>>(ow, owt, DMODEL, 0, DMODEL, 0, 0);

    // 3) v = xs @ qkv_w[:,:,2dE:]   per expert: M=32768, N=512, K=512
    gemm_h<0><<<dim3(2, 256, 4), 512, G_SMEM>>>(
        xn, DMODEL, DEXP, qvt, DEXP, (long long)DEXP * DEXP,
        v, DMODEL, DEXP, DEXP, nullptr, nullptr, nullptr);

    // 4) eo = (v @ proj + pb) * routing
    gemm_h<1><<<dim3(2, 256, 4), 512, G_SMEM>>>(
        v, DMODEL, DEXP, pjt, DEXP, (long long)DEXP * DEXP,
        eo, DMODEL, DEXP, DEXP, pb, rt, nullptr);

    // 5) out = x + eo @ out_w       M=32768, N=2048, K=2048
    gemm_h<2><<<dim3(8, 256, 1), 512, G_SMEM>>>(
        eo, DMODEL, 0, owt, DMODEL, 0,
        out, DMODEL, 0, DMODEL, nullptr, nullptr, x);
}

// round 8
// speedup vs baseline: 1.2464x; 1.2464x over previous
#include <cuda_runtime.h>
#include <cuda_fp16.h>
#include <cstdint>

// ---------------- problem constants ----------------
#define BROWS 32768
#define DMODEL 2048
#define NEXP 4
#define DEXP 512

// ---------------- device scratch (allocation-free rule) ----------------
__device__ __half g_xn [(size_t)BROWS * DMODEL];
__device__ __half g_v  [(size_t)BROWS * DMODEL];
__device__ __half g_eo [(size_t)BROWS * DMODEL];
__device__ float  g_rt [(size_t)BROWS * NEXP];
__device__ __half g_qvt[(size_t)NEXP * DEXP * DEXP];   // qkv V-slice, [e][n][k]
__device__ __half g_pjt[(size_t)NEXP * DEXP * DEXP];   // proj,        [e][n][k]
__device__ __half g_owt[(size_t)DMODEL * DMODEL];      // out_w,       [n][k]

__device__ __forceinline__ uint32_t smem_u32(const void* p) {
    uint32_t a;
    asm("{ .reg .u64 t; cvta.to.shared.u64 t, %1; cvt.u32.u64 %0, t; }" : "=r"(a) : "l"(p));
    return a;
}

#define CP16(dst, src) \
    asm volatile("cp.async.cg.shared.global [%0], [%1], 16;\n" :: "r"(dst), "l"(src))

#define LDSM_X4(r0, r1, r2, r3, addr) \
    asm volatile("ldmatrix.sync.aligned.m8n8.x4.shared.b16 {%0,%1,%2,%3}, [%4];" \
        : "=r"(r0), "=r"(r1), "=r"(r2), "=r"(r3) : "r"(addr))

// ---------------------------------------------------------------------------
// Kernel 0: RMSNorm + router softmax; writes xn as fp16 (rn)
// ---------------------------------------------------------------------------
__global__ void __launch_bounds__(256)
rmsnorm_router_kernel(const float* __restrict__ x, const float* __restrict__ nw,
                      const float* __restrict__ rw, const float* __restrict__ rb,
                      __half* __restrict__ xn, float* __restrict__ routing)
{
    __shared__ float red[8];
    __shared__ float red4[8][4];
    __shared__ float s_rn;

    const int b = blockIdx.x;
    const int tid = threadIdx.x;
    const int lane = tid & 31, warp = tid >> 5;

    const float4* xr = reinterpret_cast<const float4*>(x + (size_t)b * DMODEL);
    float4 v0 = xr[tid];
    float4 v1 = xr[tid + 256];

    float ss = v0.x*v0.x + v0.y*v0.y + v0.z*v0.z + v0.w*v0.w
             + v1.x*v1.x + v1.y*v1.y + v1.z*v1.z + v1.w*v1.w;
    #pragma unroll
    for (int o = 16; o; o >>= 1) ss += __shfl_xor_sync(0xffffffffu, ss, o);
    if (lane == 0) red[warp] = ss;
    __syncthreads();
    if (tid == 0) {
        float t = 0.f;
        #pragma unroll
        for (int i = 0; i < 8; i++) t += red[i];
        s_rn = rsqrtf(t * (1.0f / DMODEL) + 1e-6f);
    }
    __syncthreads();
    const float rn = s_rn;

    const float4* nwr = reinterpret_cast<const float4*>(nw);
    float4 w0 = nwr[tid], w1 = nwr[tid + 256];
    float4 y0 = make_float4(v0.x*rn*w0.x, v0.y*rn*w0.y, v0.z*rn*w0.z, v0.w*rn*w0.w);
    float4 y1 = make_float4(v1.x*rn*w1.x, v1.y*rn*w1.y, v1.z*rn*w1.z, v1.w*rn*w1.w);

    __half2* xo = reinterpret_cast<__half2*>(xn + (size_t)b * DMODEL);
    xo[tid * 2]             = __floats2half2_rn(y0.x, y0.y);
    xo[tid * 2 + 1]         = __floats2half2_rn(y0.z, y0.w);
    xo[(tid + 256) * 2]     = __floats2half2_rn(y1.x, y1.y);
    xo[(tid + 256) * 2 + 1] = __floats2half2_rn(y1.z, y1.w);

    const float4* rwr = reinterpret_cast<const float4*>(rw);
    float a0 = 0.f, a1 = 0.f, a2 = 0.f, a3 = 0.f;
    const int d0 = tid * 4;
    const int d1 = (tid + 256) * 4;
    float ys[8] = {y0.x, y0.y, y0.z, y0.w, y1.x, y1.y, y1.z, y1.w};
    int   ds[8] = {d0, d0+1, d0+2, d0+3, d1, d1+1, d1+2, d1+3};
    #pragma unroll
    for (int i = 0; i < 8; i++) {
        float4 w = rwr[ds[i]];
        a0 += ys[i] * w.x; a1 += ys[i] * w.y; a2 += ys[i] * w.z; a3 += ys[i] * w.w;
    }
    #pragma unroll
    for (int o = 16; o; o >>= 1) {
        a0 += __shfl_xor_sync(0xffffffffu, a0, o);
        a1 += __shfl_xor_sync(0xffffffffu, a1, o);
        a2 += __shfl_xor_sync(0xffffffffu, a2, o);
        a3 += __shfl_xor_sync(0xffffffffu, a3, o);
    }
    if (lane == 0) { red4[warp][0]=a0; red4[warp][1]=a1; red4[warp][2]=a2; red4[warp][3]=a3; }
    __syncthreads();
    if (tid == 0) {
        float l[4];
        #pragma unroll
        for (int e = 0; e < 4; e++) {
            l[e] = rb[e];
            #pragma unroll
            for (int i = 0; i < 8; i++) l[e] += red4[i][e];
        }
        float m = fmaxf(fmaxf(l[0], l[1]), fmaxf(l[2], l[3]));
        float p[4], s = 0.f;
        #pragma unroll
        for (int e = 0; e < 4; e++) { p[e] = expf(l[e] - m); s += p[e]; }
        float inv = 1.0f / s;
        #pragma unroll
        for (int e = 0; e < 4; e++) routing[(size_t)b * 4 + e] = p[e] * inv;
    }
}

// ---------------------------------------------------------------------------
// Weight transpose + fp16 round: out[e][n][k] = half(in[e][k][col_off + n])
// ---------------------------------------------------------------------------
__global__ void __launch_bounds__(256)
transpose_h(const float* __restrict__ in, __half* __restrict__ out,
            int src_ld, int col_off, int Kdim,
            long long in_es, long long out_es)
{
    __shared__ float t[32][33];
    const int e = blockIdx.z;
    in  += (long long)e * in_es;
    out += (long long)e * out_es;
    const int k0 = blockIdx.x * 32, n0 = blockIdx.y * 32;
    const int txx = threadIdx.x % 32;
    const int tyy = threadIdx.x / 32;   // 0..7
    #pragma unroll
    for (int i = 0; i < 32; i += 8)
        t[tyy + i][txx] = in[(size_t)(k0 + tyy + i) * src_ld + col_off + n0 + txx];
    __syncthreads();
    #pragma unroll
    for (int i = 0; i < 32; i += 8)
        out[(size_t)(n0 + tyy + i) * Kdim + k0 + txx] = __float2half_rn(t[txx][tyy + i]);
}

// ---------------------------------------------------------------------------
// fp16 tensor-core GEMM: C[M,N] = A[M,K] @ Bt[N,K]^T
// BM=128, BN=256, BK=64, 4-stage cp.async (wait_group 2), ldmatrix ping-pong,
// 144B pitch (conflict-free), single barrier/k-tile, cp.async spread over ks.
// 8 warps as 2(M) x 4(N): warp tile 64x64.
// MODE 0: C(half) = A@B
// MODE 1: C(half) = (A@B + bias) * routing
// MODE 2: C(float) = A@B + resid
// ---------------------------------------------------------------------------
static constexpr int G_BM = 128, G_BN = 256, G_BK = 64, G_STAGES = 4;
static constexpr int G_PITCH = 144;                         // bytes per smem row
static constexpr int G_ABYTES = G_BM * G_PITCH;             // 18432
static constexpr int G_BBYTES = G_BN * G_PITCH;             // 36864
static constexpr int G_STAGE  = G_ABYTES + G_BBYTES;        // 55296
static constexpr int G_SMEM   = G_STAGES * G_STAGE;         // 221184

template<int MODE>
__global__ void __launch_bounds__(256, 1)
gemm_h(const __half* __restrict__ A, int lda, int aColStep,
       const __half* __restrict__ Bt, int ldb, long long sB,
       void* __restrict__ Cv, int ldc, int cColStep,
       int K,
       const float* __restrict__ bias,
       const float* __restrict__ routing,
       const float* __restrict__ resid)
{
    extern __shared__ char smem[];
    const uint32_t sbase = smem_u32(smem);

    const int tid = threadIdx.x, lane = tid & 31, warp = tid >> 5;
    const int bn = blockIdx.x, bm = blockIdx.y, e = blockIdx.z;
    const int wm = warp & 1, wn = warp >> 1;
    const int m_base = wm * 64, n_base = wn * 64;

    const __half* Ag = A + (size_t)(bm * G_BM) * lda + e * aColStep;
    const __half* Bg = Bt + (long long)e * sB + (size_t)(bn * G_BN) * ldb;

    // cp.async layout: row = tid>>3 (0..31), chunk = tid&7 (16B each)
    const int arow = tid >> 3, ac = tid & 7;

    // full-stage load (prologue only)
    auto load_stage = [&](int s, int kt) {
        const uint32_t as = sbase + s * G_STAGE;
        const uint32_t bs = as + G_ABYTES;
        const int k0 = kt * G_BK;
        #pragma unroll
        for (int i = 0; i < 4; i++)
            CP16(as + (uint32_t)((arow + 32 * i) * G_PITCH + ac * 16),
                 Ag + (size_t)(arow + 32 * i) * lda + k0 + ac * 8);
        #pragma unroll
        for (int i = 0; i < 8; i++)
            CP16(bs + (uint32_t)((arow + 32 * i) * G_PITCH + ac * 16),
                 Bg + (size_t)(arow + 32 * i) * ldb + k0 + ac * 8);
        asm volatile("cp.async.commit_group;\n" ::);
    };

    // quarter-stage load: part p in 0..3 issues 1 A-chunk + 2 B-chunks
    auto load_part = [&](int s, int kt, int p) {
        const uint32_t as = sbase + s * G_STAGE;
        const uint32_t bs = as + G_ABYTES;
        const int k0 = kt * G_BK;
        CP16(as + (uint32_t)((arow + 32 * p) * G_PITCH + ac * 16),
             Ag + (size_t)(arow + 32 * p) * lda + k0 + ac * 8);
        CP16(bs + (uint32_t)((arow + 32 * (2 * p)) * G_PITCH + ac * 16),
             Bg + (size_t)(arow + 32 * (2 * p)) * ldb + k0 + ac * 8);
        CP16(bs + (uint32_t)((arow + 32 * (2 * p + 1)) * G_PITCH + ac * 16),
             Bg + (size_t)(arow + 32 * (2 * p + 1)) * ldb + k0 + ac * 8);
    };

    // ldmatrix per-thread address bases
    const int mt = lane >> 3, rr = lane & 7;
    const uint32_t aAddr0 = sbase +
        (uint32_t)((m_base + (mt & 1) * 8 + rr) * G_PITCH + (mt >> 1) * 16);
    const uint32_t bAddr0 = sbase + (uint32_t)G_ABYTES +
        (uint32_t)((n_base + (mt >> 1) * 8 + rr) * G_PITCH + (mt & 1) * 16);

    float acc[4][8][4];
    #pragma unroll
    for (int f = 0; f < 4; f++)
        #pragma unroll
        for (int g = 0; g < 8; g++)
            #pragma unroll
            for (int i = 0; i < 4; i++) acc[f][g][i] = 0.f;

    uint32_t a[2][4][4], b[2][4][4];

    const int NT = K / G_BK;
    // prologue: 3 stages in flight
    load_stage(0, 0);
    load_stage(1, 1);
    load_stage(2, 2);

    for (int kt = 0; kt < NT; kt++) {
        asm volatile("cp.async.wait_group 2;\n" ::);
        __syncthreads();

        const uint32_t so = (uint32_t)((kt & 3) * G_STAGE);
        const int tn = kt + 3;                       // tile to prefetch
        const int ts = tn & 3;
        const bool doload = (tn < NT);

        // prime frags for ks=0
        #pragma unroll
        for (int f = 0; f < 4; f++)
            LDSM_X4(a[0][f][0], a[0][f][1], a[0][f][2], a[0][f][3],
                    aAddr0 + so + (uint32_t)(f * 16 * G_PITCH));
        #pragma unroll
        for (int gp = 0; gp < 4; gp++)
            LDSM_X4(b[0][gp][0], b[0][gp][1], b[0][gp][2], b[0][gp][3],
                    bAddr0 + so + (uint32_t)(gp * 16 * G_PITCH));

        #pragma unroll
        for (int ks = 0; ks < 4; ks++) {
            const int cur = ks & 1, nxt = cur ^ 1;
            if (ks < 3) {
                const uint32_t ko = so + (uint32_t)((ks + 1) * 32);
                #pragma unroll
                for (int f = 0; f < 4; f++)
                    LDSM_X4(a[nxt][f][0], a[nxt][f][1], a[nxt][f][2], a[nxt][f][3],
                            aAddr0 + ko + (uint32_t)(f * 16 * G_PITCH));
                #pragma unroll
                for (int gp = 0; gp < 4; gp++)
                    LDSM_X4(b[nxt][gp][0], b[nxt][gp][1], b[nxt][gp][2], b[nxt][gp][3],
                            bAddr0 + ko + (uint32_t)(gp * 16 * G_PITCH));
            }
            // spread next-tile global loads: 3 cp.async per ks
            if (doload) load_part(ts, tn, ks);
            if (ks == 3)
                asm volatile("cp.async.commit_group;\n" ::);   // (empty at tail — keeps counts exact)

            #pragma unroll
            for (int f = 0; f < 4; f++)
                #pragma unroll
                for (int g = 0; g < 8; g++) {
                    float* d = acc[f][g];
                    const uint32_t b0 = b[cur][g >> 1][(g & 1) * 2];
                    const uint32_t b1 = b[cur][g >> 1][(g & 1) * 2 + 1];
                    asm volatile(
                        "mma.sync.aligned.m16n8k16.row.col.f32.f16.f16.f32 "
                        "{%0,%1,%2,%3}, {%4,%5,%6,%7}, {%8,%9}, {%0,%1,%2,%3};\n"
                        : "+f"(d[0]), "+f"(d[1]), "+f"(d[2]), "+f"(d[3])
                        : "r"(a[cur][f][0]), "r"(a[cur][f][1]),
                          "r"(a[cur][f][2]), "r"(a[cur][f][3]),
                          "r"(b0), "r"(b1));
                }
        }
    }

    // ---------------- epilogue ----------------
    const int gid = lane >> 2, tig = lane & 3;
    const int cColBase = e * cColStep + bn * G_BN;

    #pragma unroll
    for (int f = 0; f < 4; f++) {
        const size_t r0 = (size_t)bm * G_BM + m_base + f * 16 + gid;
        const size_t r1 = r0 + 8;
        float rt0 = 1.f, rt1 = 1.f;
        if (MODE == 1) {
            rt0 = routing[r0 * 4 + e];
            rt1 = routing[r1 * 4 + e];
        }
        #pragma unroll
        for (int g = 0; g < 8; g++) {
            const int ncl = n_base + g * 8 + tig * 2;   // col within block tile
            const int gc = cColBase + ncl;
            float v0 = acc[f][g][0], v1 = acc[f][g][1];
            float v2 = acc[f][g][2], v3 = acc[f][g][3];
            if (MODE == 1) {
                const float b0 = bias[e * DEXP + bn * G_BN + ncl];
                const float b1 = bias[e * DEXP + bn * G_BN + ncl + 1];
                v0 = (v0 + b0) * rt0; v1 = (v1 + b1) * rt0;
                v2 = (v2 + b0) * rt1; v3 = (v3 + b1) * rt1;
            }
            if (MODE == 2) {
                float* C = (float*)Cv;
                const float2 x0 = *reinterpret_cast<const float2*>(resid + r0 * ldc + gc);
                const float2 x1 = *reinterpret_cast<const float2*>(resid + r1 * ldc + gc);
                *reinterpret_cast<float2*>(C + r0 * ldc + gc) = make_float2(v0 + x0.x, v1 + x0.y);
                *reinterpret_cast<float2*>(C + r1 * ldc + gc) = make_float2(v2 + x1.x, v3 + x1.y);
            } else {
                __half* C = (__half*)Cv;
                *reinterpret_cast<__half2*>(C + r0 * ldc + gc) = __floats2half2_rn(v0, v1);
                *reinterpret_cast<__half2*>(C + r1 * ldc + gc) = __floats2half2_rn(v2, v3);
            }
        }
    }
}

// ---------------------------------------------------------------------------
extern "C" void kernel_launch(void* const* d_in, const int* in_sizes, int n_in,
                              void* d_out, int out_size)
{
    const float* x    = (const float*)d_in[0];
    const float* nw   = (const float*)d_in[1];
    const float* rw   = (const float*)d_in[2];
    const float* rb   = (const float*)d_in[3];
    const float* qkv  = (const float*)d_in[4];
    const float* proj = (const float*)d_in[5];
    const float* pb   = (const float*)d_in[6];
    const float* ow   = (const float*)d_in[7];
    float* out = (float*)d_out;

    __half *xn, *v, *eo, *qvt, *pjt, *owt;
    float *rt;
    cudaGetSymbolAddress((void**)&xn,  g_xn);
    cudaGetSymbolAddress((void**)&v,   g_v);
    cudaGetSymbolAddress((void**)&eo,  g_eo);
    cudaGetSymbolAddress((void**)&rt,  g_rt);
    cudaGetSymbolAddress((void**)&qvt, g_qvt);
    cudaGetSymbolAddress((void**)&pjt, g_pjt);
    cudaGetSymbolAddress((void**)&owt, g_owt);

    cudaFuncSetAttribute(gemm_h<0>, cudaFuncAttributeMaxDynamicSharedMemorySize, G_SMEM);
    cudaFuncSetAttribute(gemm_h<1>, cudaFuncAttributeMaxDynamicSharedMemorySize, G_SMEM);
    cudaFuncSetAttribute(gemm_h<2>, cudaFuncAttributeMaxDynamicSharedMemorySize, G_SMEM);

    // 1) RMSNorm + router (writes fp16 xn, fp32 routing)
    rmsnorm_router_kernel<<<BROWS, 256>>>(x, nw, rw, rb, xn, rt);

    // 2) weight transposes (+ fp16 round)
    transpose_h<<<dim3(16, 16, 4), 256>>>(qkv, qvt, 3 * DEXP, 2 * DEXP, DEXP,
                                          (long long)DEXP * 3 * DEXP, (long long)DEXP * DEXP);
    transpose_h<<<dim3(16, 16, 4), 256>>>(proj, pjt, DEXP, 0, DEXP,
                                          (long long)DEXP * DEXP, (long long)DEXP * DEXP);
    transpose_h<<<dim3(64, 64, 1), 256>>>(ow, owt, DMODEL, 0, DMODEL, 0, 0);

    // 3) v = xs @ qkv_w[:,:,2dE:]   per expert: M=32768, N=512, K=512
    gemm_h<0><<<dim3(2, 256, 4), 256, G_SMEM>>>(
        xn, DMODEL, DEXP, qvt, DEXP, (long long)DEXP * DEXP,
        v, DMODEL, DEXP, DEXP, nullptr, nullptr, nullptr);

    // 4) eo = (v @ proj + pb) * routing
    gemm_h<1><<<dim3(2, 256, 4), 256, G_SMEM>>>(
        v, DMODEL, DEXP, pjt, DEXP, (long long)DEXP * DEXP,
        eo, DMODEL, DEXP, DEXP, pb, rt, nullptr);

    // 5) out = x + eo @ out_w       M=32768, N=2048, K=2048
    gemm_h<2><<<dim3(8, 256, 1), 256, G_SMEM>>>(
        eo, DMODEL, 0, owt, DMODEL, 0,
        out, DMODEL, 0, DMODEL, nullptr, nullptr, x);
}

// round 9
// speedup vs baseline: 1.3409x; 1.0758x over previous
#include <cuda_runtime.h>
#include <cuda_fp16.h>
#include <cstdint>

// ---------------- problem constants ----------------
#define BROWS 32768
#define DMODEL 2048
#define NEXP 4
#define DEXP 512

// ---------------- device scratch (allocation-free rule) ----------------
__device__ __half g_xn [(size_t)BROWS * DMODEL];
__device__ __half g_v  [(size_t)BROWS * DMODEL];
__device__ __half g_eo [(size_t)BROWS * DMODEL];
__device__ float  g_rt [(size_t)BROWS * NEXP];
__device__ __half g_qvt[(size_t)NEXP * DEXP * DEXP];   // qkv V-slice, [e][n][k]
__device__ __half g_pjt[(size_t)NEXP * DEXP * DEXP];   // proj,        [e][n][k]
__device__ __half g_owt[(size_t)DMODEL * DMODEL];      // out_w,       [n][k]

__device__ __forceinline__ uint32_t smem_u32(const void* p) {
    uint32_t a;
    asm("{ .reg .u64 t; cvta.to.shared.u64 t, %1; cvt.u32.u64 %0, t; }" : "=r"(a) : "l"(p));
    return a;
}

#define CP16(dst, src) \
    asm volatile("cp.async.cg.shared.global [%0], [%1], 16;\n" :: "r"(dst), "l"(src))

#define LDSM_X4(r0, r1, r2, r3, addr) \
    asm volatile("ldmatrix.sync.aligned.m8n8.x4.shared.b16 {%0,%1,%2,%3}, [%4];" \
        : "=r"(r0), "=r"(r1), "=r"(r2), "=r"(r3) : "r"(addr))

// ---------------------------------------------------------------------------
// Kernel 0: RMSNorm + router softmax; writes xn as fp16 (rn)
// ---------------------------------------------------------------------------
__global__ void __launch_bounds__(256)
rmsnorm_router_kernel(const float* __restrict__ x, const float* __restrict__ nw,
                      const float* __restrict__ rw, const float* __restrict__ rb,
                      __half* __restrict__ xn, float* __restrict__ routing)
{
    __shared__ float red[8];
    __shared__ float red4[8][4];
    __shared__ float s_rn;

    const int b = blockIdx.x;
    const int tid = threadIdx.x;
    const int lane = tid & 31, warp = tid >> 5;

    const float4* xr = reinterpret_cast<const float4*>(x + (size_t)b * DMODEL);
    float4 v0 = xr[tid];
    float4 v1 = xr[tid + 256];

    float ss = v0.x*v0.x + v0.y*v0.y + v0.z*v0.z + v0.w*v0.w
             + v1.x*v1.x + v1.y*v1.y + v1.z*v1.z + v1.w*v1.w;
    #pragma unroll
    for (int o = 16; o; o >>= 1) ss += __shfl_xor_sync(0xffffffffu, ss, o);
    if (lane == 0) red[warp] = ss;
    __syncthreads();
    if (tid == 0) {
        float t = 0.f;
        #pragma unroll
        for (int i = 0; i < 8; i++) t += red[i];
        s_rn = rsqrtf(t * (1.0f / DMODEL) + 1e-6f);
    }
    __syncthreads();
    const float rn = s_rn;

    const float4* nwr = reinterpret_cast<const float4*>(nw);
    float4 w0 = nwr[tid], w1 = nwr[tid + 256];
    float4 y0 = make_float4(v0.x*rn*w0.x, v0.y*rn*w0.y, v0.z*rn*w0.z, v0.w*rn*w0.w);
    float4 y1 = make_float4(v1.x*rn*w1.x, v1.y*rn*w1.y, v1.z*rn*w1.z, v1.w*rn*w1.w);

    __half2* xo = reinterpret_cast<__half2*>(xn + (size_t)b * DMODEL);
    xo[tid * 2]             = __floats2half2_rn(y0.x, y0.y);
    xo[tid * 2 + 1]         = __floats2half2_rn(y0.z, y0.w);
    xo[(tid + 256) * 2]     = __floats2half2_rn(y1.x, y1.y);
    xo[(tid + 256) * 2 + 1] = __floats2half2_rn(y1.z, y1.w);

    const float4* rwr = reinterpret_cast<const float4*>(rw);
    float a0 = 0.f, a1 = 0.f, a2 = 0.f, a3 = 0.f;
    const int d0 = tid * 4;
    const int d1 = (tid + 256) * 4;
    float ys[8] = {y0.x, y0.y, y0.z, y0.w, y1.x, y1.y, y1.z, y1.w};
    int   ds[8] = {d0, d0+1, d0+2, d0+3, d1, d1+1, d1+2, d1+3};
    #pragma unroll
    for (int i = 0; i < 8; i++) {
        float4 w = rwr[ds[i]];
        a0 += ys[i] * w.x; a1 += ys[i] * w.y; a2 += ys[i] * w.z; a3 += ys[i] * w.w;
    }
    #pragma unroll
    for (int o = 16; o; o >>= 1) {
        a0 += __shfl_xor_sync(0xffffffffu, a0, o);
        a1 += __shfl_xor_sync(0xffffffffu, a1, o);
        a2 += __shfl_xor_sync(0xffffffffu, a2, o);
        a3 += __shfl_xor_sync(0xffffffffu, a3, o);
    }
    if (lane == 0) { red4[warp][0]=a0; red4[warp][1]=a1; red4[warp][2]=a2; red4[warp][3]=a3; }
    __syncthreads();
    if (tid == 0) {
        float l[4];
        #pragma unroll
        for (int e = 0; e < 4; e++) {
            l[e] = rb[e];
            #pragma unroll
            for (int i = 0; i < 8; i++) l[e] += red4[i][e];
        }
        float m = fmaxf(fmaxf(l[0], l[1]), fmaxf(l[2], l[3]));
        float p[4], s = 0.f;
        #pragma unroll
        for (int e = 0; e < 4; e++) { p[e] = expf(l[e] - m); s += p[e]; }
        float inv = 1.0f / s;
        #pragma unroll
        for (int e = 0; e < 4; e++) routing[(size_t)b * 4 + e] = p[e] * inv;
    }
}

// ---------------------------------------------------------------------------
// Weight transpose + fp16 round: out[e][n][k] = half(in[e][k][col_off + n])
// ---------------------------------------------------------------------------
__global__ void __launch_bounds__(256)
transpose_h(const float* __restrict__ in, __half* __restrict__ out,
            int src_ld, int col_off, int Kdim,
            long long in_es, long long out_es)
{
    __shared__ float t[32][33];
    const int e = blockIdx.z;
    in  += (long long)e * in_es;
    out += (long long)e * out_es;
    const int k0 = blockIdx.x * 32, n0 = blockIdx.y * 32;
    const int txx = threadIdx.x % 32;
    const int tyy = threadIdx.x / 32;   // 0..7
    #pragma unroll
    for (int i = 0; i < 32; i += 8)
        t[tyy + i][txx] = in[(size_t)(k0 + tyy + i) * src_ld + col_off + n0 + txx];
    __syncthreads();
    #pragma unroll
    for (int i = 0; i < 32; i += 8)
        out[(size_t)(n0 + tyy + i) * Kdim + k0 + txx] = __float2half_rn(t[txx][tyy + i]);
}

// ---------------------------------------------------------------------------
// fp16 tensor-core GEMM: C[M,N] = A[M,K] @ Bt[N,K]^T
// BM=128, BN=256, BK=64, 4-stage cp.async, ldmatrix ping-pong ACROSS tiles,
// barrier buried at ks==2 (no serial top-of-loop), 144B pitch.
// 8 warps as 2(M) x 4(N): warp tile 64x64.
// MODE 0: C(half) = A@B
// MODE 1: C(half) = (A@B + bias) * routing
// MODE 2: C(float) = A@B + resid
// ---------------------------------------------------------------------------
static constexpr int G_BM = 128, G_BN = 256, G_BK = 64, G_STAGES = 4;
static constexpr int G_PITCH = 144;                         // bytes per smem row
static constexpr int G_ABYTES = G_BM * G_PITCH;             // 18432
static constexpr int G_BBYTES = G_BN * G_PITCH;             // 36864
static constexpr int G_STAGE  = G_ABYTES + G_BBYTES;        // 55296
static constexpr int G_SMEM   = G_STAGES * G_STAGE;         // 221184

template<int MODE>
__global__ void __launch_bounds__(256, 1)
gemm_h(const __half* __restrict__ A, int lda, int aColStep,
       const __half* __restrict__ Bt, int ldb, long long sB,
       void* __restrict__ Cv, int ldc, int cColStep,
       int K,
       const float* __restrict__ bias,
       const float* __restrict__ routing,
       const float* __restrict__ resid)
{
    extern __shared__ char smem[];
    const uint32_t sbase = smem_u32(smem);

    const int tid = threadIdx.x, lane = tid & 31, warp = tid >> 5;
    const int bn = blockIdx.x, bm = blockIdx.y, e = blockIdx.z;
    const int wm = warp & 1, wn = warp >> 1;
    const int m_base = wm * 64, n_base = wn * 64;

    const __half* Ag = A + (size_t)(bm * G_BM) * lda + e * aColStep;
    const __half* Bg = Bt + (long long)e * sB + (size_t)(bn * G_BN) * ldb;

    // cp.async layout: row = tid>>3 (0..31), chunk = tid&7 (16B each)
    const int arow = tid >> 3, ac = tid & 7;

    auto load_stage = [&](int s, int kt) {
        const uint32_t as = sbase + s * G_STAGE;
        const uint32_t bs = as + G_ABYTES;
        const int k0 = kt * G_BK;
        #pragma unroll
        for (int i = 0; i < 4; i++)
            CP16(as + (uint32_t)((arow + 32 * i) * G_PITCH + ac * 16),
                 Ag + (size_t)(arow + 32 * i) * lda + k0 + ac * 8);
        #pragma unroll
        for (int i = 0; i < 8; i++)
            CP16(bs + (uint32_t)((arow + 32 * i) * G_PITCH + ac * 16),
                 Bg + (size_t)(arow + 32 * i) * ldb + k0 + ac * 8);
        asm volatile("cp.async.commit_group;\n" ::);
    };

    // half-stage load: part p in 0..1 issues 2 A-chunks + 4 B-chunks
    auto load_half = [&](int s, int kt, int p) {
        const uint32_t as = sbase + s * G_STAGE;
        const uint32_t bs = as + G_ABYTES;
        const int k0 = kt * G_BK;
        #pragma unroll
        for (int i = 0; i < 2; i++)
            CP16(as + (uint32_t)((arow + 32 * (2 * p + i)) * G_PITCH + ac * 16),
                 Ag + (size_t)(arow + 32 * (2 * p + i)) * lda + k0 + ac * 8);
        #pragma unroll
        for (int i = 0; i < 4; i++)
            CP16(bs + (uint32_t)((arow + 32 * (4 * p + i)) * G_PITCH + ac * 16),
                 Bg + (size_t)(arow + 32 * (4 * p + i)) * ldb + k0 + ac * 8);
    };

    // ldmatrix per-thread address bases
    const int mt = lane >> 3, rr = lane & 7;
    const uint32_t aAddr0 = sbase +
        (uint32_t)((m_base + (mt & 1) * 8 + rr) * G_PITCH + (mt >> 1) * 16);
    const uint32_t bAddr0 = sbase + (uint32_t)G_ABYTES +
        (uint32_t)((n_base + (mt >> 1) * 8 + rr) * G_PITCH + (mt & 1) * 16);

    float acc[4][8][4];
    #pragma unroll
    for (int f = 0; f < 4; f++)
        #pragma unroll
        for (int g = 0; g < 8; g++)
            #pragma unroll
            for (int i = 0; i < 4; i++) acc[f][g][i] = 0.f;

    uint32_t a[2][4][4], b[2][4][4];

    const int NT = K / G_BK;
    // prologue: 3 stages in flight; prime frags for tile0/ks0
    load_stage(0, 0);
    load_stage(1, 1);
    load_stage(2, 2);
    asm volatile("cp.async.wait_group 2;\n" ::);
    __syncthreads();
    #pragma unroll
    for (int f = 0; f < 4; f++)
        LDSM_X4(a[0][f][0], a[0][f][1], a[0][f][2], a[0][f][3],
                aAddr0 + (uint32_t)(f * 16 * G_PITCH));
    #pragma unroll
    for (int gp = 0; gp < 4; gp++)
        LDSM_X4(b[0][gp][0], b[0][gp][1], b[0][gp][2], b[0][gp][3],
                bAddr0 + (uint32_t)(gp * 16 * G_PITCH));

    for (int kt = 0; kt < NT; kt++) {
        const uint32_t so = (uint32_t)((kt & 3) * G_STAGE);
        const int tn = kt + 3;                       // tile to prefetch
        const int ts = tn & 3;
        const bool doload = (tn < NT);

        #pragma unroll
        for (int ks = 0; ks < 4; ks++) {
            const int cur = ks & 1, nxt = cur ^ 1;

            if (ks < 3) {
                // frags for next ks of this tile
                const uint32_t ko = so + (uint32_t)((ks + 1) * 32);
                #pragma unroll
                for (int f = 0; f < 4; f++)
                    LDSM_X4(a[nxt][f][0], a[nxt][f][1], a[nxt][f][2], a[nxt][f][3],
                            aAddr0 + ko + (uint32_t)(f * 16 * G_PITCH));
                #pragma unroll
                for (int gp = 0; gp < 4; gp++)
                    LDSM_X4(b[nxt][gp][0], b[nxt][gp][1], b[nxt][gp][2], b[nxt][gp][3],
                            bAddr0 + ko + (uint32_t)(gp * 16 * G_PITCH));
            } else if (kt + 1 < NT) {
                // prime ks0 frags of NEXT tile (data certified at ks==2 barrier)
                const uint32_t so2 = (uint32_t)(((kt + 1) & 3) * G_STAGE);
                #pragma unroll
                for (int f = 0; f < 4; f++)
                    LDSM_X4(a[nxt][f][0], a[nxt][f][1], a[nxt][f][2], a[nxt][f][3],
                            aAddr0 + so2 + (uint32_t)(f * 16 * G_PITCH));
                #pragma unroll
                for (int gp = 0; gp < 4; gp++)
                    LDSM_X4(b[nxt][gp][0], b[nxt][gp][1], b[nxt][gp][2], b[nxt][gp][3],
                            bAddr0 + so2 + (uint32_t)(gp * 16 * G_PITCH));
            }

            if (ks == 2) {
                // certifies tile kt+1 complete AND all warps past tile kt-1 reads
                asm volatile("cp.async.wait_group 1;\n" ::);
                __syncthreads();
                if (doload) load_half(ts, tn, 0);
            }
            if (ks == 3) {
                if (doload) load_half(ts, tn, 1);
                asm volatile("cp.async.commit_group;\n" ::);  // may be empty at tail
            }

            #pragma unroll
            for (int f = 0; f < 4; f++)
                #pragma unroll
                for (int g = 0; g < 8; g++) {
                    float* d = acc[f][g];
                    const uint32_t b0 = b[cur][g >> 1][(g & 1) * 2];
                    const uint32_t b1 = b[cur][g >> 1][(g & 1) * 2 + 1];
                    asm volatile(
                        "mma.sync.aligned.m16n8k16.row.col.f32.f16.f16.f32 "
                        "{%0,%1,%2,%3}, {%4,%5,%6,%7}, {%8,%9}, {%0,%1,%2,%3};\n"
                        : "+f"(d[0]), "+f"(d[1]), "+f"(d[2]), "+f"(d[3])
                        : "r"(a[cur][f][0]), "r"(a[cur][f][1]),
                          "r"(a[cur][f][2]), "r"(a[cur][f][3]),
                          "r"(b0), "r"(b1));
                }
        }
    }

    // ---------------- epilogue ----------------
    const int gid = lane >> 2, tig = lane & 3;
    const int cColBase = e * cColStep + bn * G_BN;

    #pragma unroll
    for (int f = 0; f < 4; f++) {
        const size_t r0 = (size_t)bm * G_BM + m_base + f * 16 + gid;
        const size_t r1 = r0 + 8;
        float rt0 = 1.f, rt1 = 1.f;
        if (MODE == 1) {
            rt0 = routing[r0 * 4 + e];
            rt1 = routing[r1 * 4 + e];
        }
        #pragma unroll
        for (int g = 0; g < 8; g++) {
            const int ncl = n_base + g * 8 + tig * 2;   // col within block tile
            const int gc = cColBase + ncl;
            float v0 = acc[f][g][0], v1 = acc[f][g][1];
            float v2 = acc[f][g][2], v3 = acc[f][g][3];
            if (MODE == 1) {
                const float b0 = bias[e * DEXP + bn * G_BN + ncl];
                const float b1 = bias[e * DEXP + bn * G_BN + ncl + 1];
                v0 = (v0 + b0) * rt0; v1 = (v1 + b1) * rt0;
                v2 = (v2 + b0) * rt1; v3 = (v3 + b1) * rt1;
            }
            if (MODE == 2) {
                float* C = (float*)Cv;
                const float2 x0 = *reinterpret_cast<const float2*>(resid + r0 * ldc + gc);
                const float2 x1 = *reinterpret_cast<const float2*>(resid + r1 * ldc + gc);
                *reinterpret_cast<float2*>(C + r0 * ldc + gc) = make_float2(v0 + x0.x, v1 + x0.y);
                *reinterpret_cast<float2*>(C + r1 * ldc + gc) = make_float2(v2 + x1.x, v3 + x1.y);
            } else {
                __half* C = (__half*)Cv;
                *reinterpret_cast<__half2*>(C + r0 * ldc + gc) = __floats2half2_rn(v0, v1);
                *reinterpret_cast<__half2*>(C + r1 * ldc + gc) = __floats2half2_rn(v2, v3);
            }
        }
    }
}

// ---------------------------------------------------------------------------
extern "C" void kernel_launch(void* const* d_in, const int* in_sizes, int n_in,
                              void* d_out, int out_size)
{
    const float* x    = (const float*)d_in[0];
    const float* nw   = (const float*)d_in[1];
    const float* rw   = (const float*)d_in[2];
    const float* rb   = (const float*)d_in[3];
    const float* qkv  = (const float*)d_in[4];
    const float* proj = (const float*)d_in[5];
    const float* pb   = (const float*)d_in[6];
    const float* ow   = (const float*)d_in[7];
    float* out = (float*)d_out;

    __half *xn, *v, *eo, *qvt, *pjt, *owt;
    float *rt;
    cudaGetSymbolAddress((void**)&xn,  g_xn);
    cudaGetSymbolAddress((void**)&v,   g_v);
    cudaGetSymbolAddress((void**)&eo,  g_eo);
    cudaGetSymbolAddress((void**)&rt,  g_rt);
    cudaGetSymbolAddress((void**)&qvt, g_qvt);
    cudaGetSymbolAddress((void**)&pjt, g_pjt);
    cudaGetSymbolAddress((void**)&owt, g_owt);

    cudaFuncSetAttribute(gemm_h<0>, cudaFuncAttributeMaxDynamicSharedMemorySize, G_SMEM);
    cudaFuncSetAttribute(gemm_h<1>, cudaFuncAttributeMaxDynamicSharedMemorySize, G_SMEM);
    cudaFuncSetAttribute(gemm_h<2>, cudaFuncAttributeMaxDynamicSharedMemorySize, G_SMEM);

    // 1) RMSNorm + router (writes fp16 xn, fp32 routing)
    rmsnorm_router_kernel<<<BROWS, 256>>>(x, nw, rw, rb, xn, rt);

    // 2) weight transposes (+ fp16 round)
    transpose_h<<<dim3(16, 16, 4), 256>>>(qkv, qvt, 3 * DEXP, 2 * DEXP, DEXP,
                                          (long long)DEXP * 3 * DEXP, (long long)DEXP * DEXP);
    transpose_h<<<dim3(16, 16, 4), 256>>>(proj, pjt, DEXP, 0, DEXP,
                                          (long long)DEXP * DEXP, (long long)DEXP * DEXP);
    transpose_h<<<dim3(64, 64, 1), 256>>>(ow, owt, DMODEL, 0, DMODEL, 0, 0);

    // 3) v = xs @ qkv_w[:,:,2dE:]   per expert: M=32768, N=512, K=512
    gemm_h<0><<<dim3(2, 256, 4), 256, G_SMEM>>>(
        xn, DMODEL, DEXP, qvt, DEXP, (long long)DEXP * DEXP,
        v, DMODEL, DEXP, DEXP, nullptr, nullptr, nullptr);

    // 4) eo = (v @ proj + pb) * routing
    gemm_h<1><<<dim3(2, 256, 4), 256, G_SMEM>>>(
        v, DMODEL, DEXP, pjt, DEXP, (long long)DEXP * DEXP,
        eo, DMODEL, DEXP, DEXP, pb, rt, nullptr);

    // 5) out = x + eo @ out_w       M=32768, N=2048, K=2048
    gemm_h<2><<<dim3(8, 256, 1), 256, G_SMEM>>>(
        eo, DMODEL, 0, owt, DMODEL, 0,
        out, DMODEL, 0, DMODEL, nullptr, nullptr, x);
}

// round 11
// speedup vs baseline: 1.3708x; 1.0224x over previous
#include <cuda_runtime.h>
#include <cuda_fp16.h>
#include <cstdint>

// ---------------- problem constants ----------------
#define BROWS 32768
#define DMODEL 2048
#define NEXP 4
#define DEXP 512

// ---------------- device scratch (allocation-free rule) ----------------
__device__ __half g_xn [(size_t)BROWS * DMODEL];
__device__ __half g_v  [(size_t)BROWS * DMODEL];
__device__ __half g_eo [(size_t)BROWS * DMODEL];
__device__ float  g_rt [(size_t)BROWS * NEXP];
__device__ __half g_qvt[(size_t)NEXP * DEXP * DEXP];   // qkv V-slice, [e][n][k]
__device__ __half g_pjt[(size_t)NEXP * DEXP * DEXP];   // proj,        [e][n][k]
__device__ __half g_owt[(size_t)DMODEL * DMODEL];      // out_w,       [n][k]

__device__ __forceinline__ uint32_t smem_u32(const void* p) {
    uint32_t a;
    asm("{ .reg .u64 t; cvta.to.shared.u64 t, %1; cvt.u32.u64 %0, t; }" : "=r"(a) : "l"(p));
    return a;
}

#define CP16(dst, src) \
    asm volatile("cp.async.cg.shared.global [%0], [%1], 16;\n" :: "r"(dst), "l"(src))

#define LDSM_X4(r0, r1, r2, r3, addr) \
    asm volatile("ldmatrix.sync.aligned.m8n8.x4.shared.b16 {%0,%1,%2,%3}, [%4];" \
        : "=r"(r0), "=r"(r1), "=r"(r2), "=r"(r3) : "r"(addr))

// ---------------------------------------------------------------------------
// Kernel 0: RMSNorm only; writes xn as fp16 (rn). Pure streaming.
// ---------------------------------------------------------------------------
__global__ void __launch_bounds__(256)
rmsnorm_kernel(const float* __restrict__ x, const float* __restrict__ nw,
               __half* __restrict__ xn)
{
    __shared__ float red[8];
    __shared__ float s_rn;

    const int b = blockIdx.x;
    const int tid = threadIdx.x;
    const int lane = tid & 31, warp = tid >> 5;

    const float4* xr = reinterpret_cast<const float4*>(x + (size_t)b * DMODEL);
    float4 v0 = xr[tid];
    float4 v1 = xr[tid + 256];

    float ss = v0.x*v0.x + v0.y*v0.y + v0.z*v0.z + v0.w*v0.w
             + v1.x*v1.x + v1.y*v1.y + v1.z*v1.z + v1.w*v1.w;
    #pragma unroll
    for (int o = 16; o; o >>= 1) ss += __shfl_xor_sync(0xffffffffu, ss, o);
    if (lane == 0) red[warp] = ss;
    __syncthreads();
    if (tid == 0) {
        float t = 0.f;
        #pragma unroll
        for (int i = 0; i < 8; i++) t += red[i];
        s_rn = rsqrtf(t * (1.0f / DMODEL) + 1e-6f);
    }
    __syncthreads();
    const float rn = s_rn;

    const float4* nwr = reinterpret_cast<const float4*>(nw);
    float4 w0 = nwr[tid], w1 = nwr[tid + 256];
    float4 y0 = make_float4(v0.x*rn*w0.x, v0.y*rn*w0.y, v0.z*rn*w0.z, v0.w*rn*w0.w);
    float4 y1 = make_float4(v1.x*rn*w1.x, v1.y*rn*w1.y, v1.z*rn*w1.z, v1.w*rn*w1.w);

    __half2* xo = reinterpret_cast<__half2*>(xn + (size_t)b * DMODEL);
    xo[tid * 2]             = __floats2half2_rn(y0.x, y0.y);
    xo[tid * 2 + 1]         = __floats2half2_rn(y0.z, y0.w);
    xo[(tid + 256) * 2]     = __floats2half2_rn(y1.x, y1.y);
    xo[(tid + 256) * 2 + 1] = __floats2half2_rn(y1.z, y1.w);
}

// ---------------------------------------------------------------------------
// Kernel 0b: router softmax from fp16 xn. Warp handles 4 rows; rw stays L1-hot.
// ---------------------------------------------------------------------------
__global__ void __launch_bounds__(256)
router_kernel(const __half* __restrict__ xn, const float* __restrict__ rw,
              const float* __restrict__ rb, float* __restrict__ routing)
{
    const int lane = threadIdx.x & 31, warp = threadIdx.x >> 5;
    const size_t row0 = (size_t)blockIdx.x * 32 + warp * 4;
    const float4* rw4 = reinterpret_cast<const float4*>(rw);
    const float b0 = rb[0], b1 = rb[1], b2 = rb[2], b3 = rb[3];

    #pragma unroll
    for (int r = 0; r < 4; r++) {
        const size_t row = row0 + r;
        const __half2* xr = reinterpret_cast<const __half2*>(xn + row * DMODEL);
        float a0 = 0.f, a1 = 0.f, a2 = 0.f, a3 = 0.f;
        #pragma unroll 4
        for (int it = 0; it < 32; it++) {
            const int d2 = lane + 32 * it;          // half2 index
            const float2 f = __half22float2(xr[d2]);
            const float4 wA = rw4[2 * d2];
            const float4 wB = rw4[2 * d2 + 1];
            a0 += f.x * wA.x + f.y * wB.x;
            a1 += f.x * wA.y + f.y * wB.y;
            a2 += f.x * wA.z + f.y * wB.z;
            a3 += f.x * wA.w + f.y * wB.w;
        }
        #pragma unroll
        for (int o = 16; o; o >>= 1) {
            a0 += __shfl_xor_sync(0xffffffffu, a0, o);
            a1 += __shfl_xor_sync(0xffffffffu, a1, o);
            a2 += __shfl_xor_sync(0xffffffffu, a2, o);
            a3 += __shfl_xor_sync(0xffffffffu, a3, o);
        }
        if (lane == 0) {
            float l0 = a0 + b0, l1 = a1 + b1, l2 = a2 + b2, l3 = a3 + b3;
            const float m = fmaxf(fmaxf(l0, l1), fmaxf(l2, l3));
            const float p0 = expf(l0 - m), p1 = expf(l1 - m);
            const float p2 = expf(l2 - m), p3 = expf(l3 - m);
            const float inv = 1.0f / (p0 + p1 + p2 + p3);
            float4* ro = reinterpret_cast<float4*>(routing + row * 4);
            *ro = make_float4(p0 * inv, p1 * inv, p2 * inv, p3 * inv);
        }
    }
}

// ---------------------------------------------------------------------------
// Weight transpose + fp16 round: out[e][n][k] = half(in[e][k][col_off + n])
// ---------------------------------------------------------------------------
__global__ void __launch_bounds__(256)
transpose_h(const float* __restrict__ in, __half* __restrict__ out,
            int src_ld, int col_off, int Kdim,
            long long in_es, long long out_es)
{
    __shared__ float t[32][33];
    const int e = blockIdx.z;
    in  += (long long)e * in_es;
    out += (long long)e * out_es;
    const int k0 = blockIdx.x * 32, n0 = blockIdx.y * 32;
    const int txx = threadIdx.x % 32;
    const int tyy = threadIdx.x / 32;   // 0..7
    #pragma unroll
    for (int i = 0; i < 32; i += 8)
        t[tyy + i][txx] = in[(size_t)(k0 + tyy + i) * src_ld + col_off + n0 + txx];
    __syncthreads();
    #pragma unroll
    for (int i = 0; i < 32; i += 8)
        out[(size_t)(n0 + tyy + i) * Kdim + k0 + txx] = __float2half_rn(t[txx][tyy + i]);
}

// ---------------------------------------------------------------------------
// fp16 tensor-core GEMM: C[M,N] = A[M,K] @ Bt[N,K]^T
// BM=128, BN=256, BK=64, 4-stage cp.async, ldmatrix ping-pong ACROSS tiles,
// barrier buried at ks==2 (no serial top-of-loop), 144B pitch.
// 8 warps as 2(M) x 4(N): warp tile 64x64.
// MODE 0: C(half) = A@B
// MODE 1: C(half) = (A@B + bias) * routing
// MODE 2: C(float) = A@B + resid
// ---------------------------------------------------------------------------
static constexpr int G_BM = 128, G_BN = 256, G_BK = 64, G_STAGES = 4;
static constexpr int G_PITCH = 144;                         // bytes per smem row
static constexpr int G_ABYTES = G_BM * G_PITCH;             // 18432
static constexpr int G_BBYTES = G_BN * G_PITCH;             // 36864
static constexpr int G_STAGE  = G_ABYTES + G_BBYTES;        // 55296
static constexpr int G_SMEM   = G_STAGES * G_STAGE;         // 221184

template<int MODE>
__global__ void __launch_bounds__(256, 1)
gemm_h(const __half* __restrict__ A, int lda, int aColStep,
       const __half* __restrict__ Bt, int ldb, long long sB,
       void* __restrict__ Cv, int ldc, int cColStep,
       int K,
       const float* __restrict__ bias,
       const float* __restrict__ routing,
       const float* __restrict__ resid)
{
    extern __shared__ char smem[];
    const uint32_t sbase = smem_u32(smem);

    const int tid = threadIdx.x, lane = tid & 31, warp = tid >> 5;
    const int bn = blockIdx.x, bm = blockIdx.y, e = blockIdx.z;
    const int wm = warp & 1, wn = warp >> 1;
    const int m_base = wm * 64, n_base = wn * 64;

    const __half* Ag = A + (size_t)(bm * G_BM) * lda + e * aColStep;
    const __half* Bg = Bt + (long long)e * sB + (size_t)(bn * G_BN) * ldb;

    // cp.async layout: row = tid>>3 (0..31), chunk = tid&7 (16B each)
    const int arow = tid >> 3, ac = tid & 7;

    auto load_stage = [&](int s, int kt) {
        const uint32_t as = sbase + s * G_STAGE;
        const uint32_t bs = as + G_ABYTES;
        const int k0 = kt * G_BK;
        #pragma unroll
        for (int i = 0; i < 4; i++)
            CP16(as + (uint32_t)((arow + 32 * i) * G_PITCH + ac * 16),
                 Ag + (size_t)(arow + 32 * i) * lda + k0 + ac * 8);
        #pragma unroll
        for (int i = 0; i < 8; i++)
            CP16(bs + (uint32_t)((arow + 32 * i) * G_PITCH + ac * 16),
                 Bg + (size_t)(arow + 32 * i) * ldb + k0 + ac * 8);
        asm volatile("cp.async.commit_group;\n" ::);
    };

    // half-stage load: part p in 0..1 issues 2 A-chunks + 4 B-chunks
    auto load_half = [&](int s, int kt, int p) {
        const uint32_t as = sbase + s * G_STAGE;
        const uint32_t bs = as + G_ABYTES;
        const int k0 = kt * G_BK;
        #pragma unroll
        for (int i = 0; i < 2; i++)
            CP16(as + (uint32_t)((arow + 32 * (2 * p + i)) * G_PITCH + ac * 16),
                 Ag + (size_t)(arow + 32 * (2 * p + i)) * lda + k0 + ac * 8);
        #pragma unroll
        for (int i = 0; i < 4; i++)
            CP16(bs + (uint32_t)((arow + 32 * (4 * p + i)) * G_PITCH + ac * 16),
                 Bg + (size_t)(arow + 32 * (4 * p + i)) * ldb + k0 + ac * 8);
    };

    // ldmatrix per-thread address bases
    const int mt = lane >> 3, rr = lane & 7;
    const uint32_t aAddr0 = sbase +
        (uint32_t)((m_base + (mt & 1) * 8 + rr) * G_PITCH + (mt >> 1) * 16);
    const uint32_t bAddr0 = sbase + (uint32_t)G_ABYTES +
        (uint32_t)((n_base + (mt >> 1) * 8 + rr) * G_PITCH + (mt & 1) * 16);

    float acc[4][8][4];
    #pragma unroll
    for (int f = 0; f < 4; f++)
        #pragma unroll
        for (int g = 0; g < 8; g++)
            #pragma unroll
            for (int i = 0; i < 4; i++) acc[f][g][i] = 0.f;

    uint32_t a[2][4][4], b[2][4][4];

    const int NT = K / G_BK;
    // prologue: 3 stages in flight; prime frags for tile0/ks0
    load_stage(0, 0);
    load_stage(1, 1);
    load_stage(2, 2);
    asm volatile("cp.async.wait_group 2;\n" ::);
    __syncthreads();
    #pragma unroll
    for (int f = 0; f < 4; f++)
        LDSM_X4(a[0][f][0], a[0][f][1], a[0][f][2], a[0][f][3],
                aAddr0 + (uint32_t)(f * 16 * G_PITCH));
    #pragma unroll
    for (int gp = 0; gp < 4; gp++)
        LDSM_X4(b[0][gp][0], b[0][gp][1], b[0][gp][2], b[0][gp][3],
                bAddr0 + (uint32_t)(gp * 16 * G_PITCH));

    for (int kt = 0; kt < NT; kt++) {
        const uint32_t so = (uint32_t)((kt & 3) * G_STAGE);
        const int tn = kt + 3;                       // tile to prefetch
        const int ts = tn & 3;
        const bool doload = (tn < NT);

        #pragma unroll
        for (int ks = 0; ks < 4; ks++) {
            const int cur = ks & 1, nxt = cur ^ 1;

            if (ks < 3) {
                // frags for next ks of this tile
                const uint32_t ko = so + (uint32_t)((ks + 1) * 32);
                #pragma unroll
                for (int f = 0; f < 4; f++)
                    LDSM_X4(a[nxt][f][0], a[nxt][f][1], a[nxt][f][2], a[nxt][f][3],
                            aAddr0 + ko + (uint32_t)(f * 16 * G_PITCH));
                #pragma unroll
                for (int gp = 0; gp < 4; gp++)
                    LDSM_X4(b[nxt][gp][0], b[nxt][gp][1], b[nxt][gp][2], b[nxt][gp][3],
                            bAddr0 + ko + (uint32_t)(gp * 16 * G_PITCH));
            } else if (kt + 1 < NT) {
                // prime ks0 frags of NEXT tile (data certified at ks==2 barrier)
                const uint32_t so2 = (uint32_t)(((kt + 1) & 3) * G_STAGE);
                #pragma unroll
                for (int f = 0; f < 4; f++)
                    LDSM_X4(a[nxt][f][0], a[nxt][f][1], a[nxt][f][2], a[nxt][f][3],
                            aAddr0 + so2 + (uint32_t)(f * 16 * G_PITCH));
                #pragma unroll
                for (int gp = 0; gp < 4; gp++)
                    LDSM_X4(b[nxt][gp][0], b[nxt][gp][1], b[nxt][gp][2], b[nxt][gp][3],
                            bAddr0 + so2 + (uint32_t)(gp * 16 * G_PITCH));
            }

            if (ks == 2) {
                // certifies tile kt+1 complete AND all warps past tile kt-1 reads
                asm volatile("cp.async.wait_group 1;\n" ::);
                __syncthreads();
                if (doload) load_half(ts, tn, 0);
            }
            if (ks == 3) {
                if (doload) load_half(ts, tn, 1);
                asm volatile("cp.async.commit_group;\n" ::);  // may be empty at tail
            }

            #pragma unroll
            for (int f = 0; f < 4; f++)
                #pragma unroll
                for (int g = 0; g < 8; g++) {
                    float* d = acc[f][g];
                    const uint32_t b0 = b[cur][g >> 1][(g & 1) * 2];
                    const uint32_t b1 = b[cur][g >> 1][(g & 1) * 2 + 1];
                    asm volatile(
                        "mma.sync.aligned.m16n8k16.row.col.f32.f16.f16.f32 "
                        "{%0,%1,%2,%3}, {%4,%5,%6,%7}, {%8,%9}, {%0,%1,%2,%3};\n"
                        : "+f"(d[0]), "+f"(d[1]), "+f"(d[2]), "+f"(d[3])
                        : "r"(a[cur][f][0]), "r"(a[cur][f][1]),
                          "r"(a[cur][f][2]), "r"(a[cur][f][3]),
                          "r"(b0), "r"(b1));
                }
        }
    }

    // ---------------- epilogue ----------------
    const int gid = lane >> 2, tig = lane & 3;
    const int cColBase = e * cColStep + bn * G_BN;

    #pragma unroll
    for (int f = 0; f < 4; f++) {
        const size_t r0 = (size_t)bm * G_BM + m_base + f * 16 + gid;
        const size_t r1 = r0 + 8;
        float rt0 = 1.f, rt1 = 1.f;
        if (MODE == 1) {
            rt0 = routing[r0 * 4 + e];
            rt1 = routing[r1 * 4 + e];
        }
        #pragma unroll
        for (int g = 0; g < 8; g++) {
            const int ncl = n_base + g * 8 + tig * 2;   // col within block tile
            const int gc = cColBase + ncl;
            float v0 = acc[f][g][0], v1 = acc[f][g][1];
            float v2 = acc[f][g][2], v3 = acc[f][g][3];
            if (MODE == 1) {
                const float b0 = bias[e * DEXP + bn * G_BN + ncl];
                const float b1 = bias[e * DEXP + bn * G_BN + ncl + 1];
                v0 = (v0 + b0) * rt0; v1 = (v1 + b1) * rt0;
                v2 = (v2 + b0) * rt1; v3 = (v3 + b1) * rt1;
            }
            if (MODE == 2) {
                float* C = (float*)Cv;
                const float2 x0 = *reinterpret_cast<const float2*>(resid + r0 * ldc + gc);
                const float2 x1 = *reinterpret_cast<const float2*>(resid + r1 * ldc + gc);
                *reinterpret_cast<float2*>(C + r0 * ldc + gc) = make_float2(v0 + x0.x, v1 + x0.y);
                *reinterpret_cast<float2*>(C + r1 * ldc + gc) = make_float2(v2 + x1.x, v3 + x1.y);
            } else {
                __half* C = (__half*)Cv;
                *reinterpret_cast<__half2*>(C + r0 * ldc + gc) = __floats2half2_rn(v0, v1);
                *reinterpret_cast<__half2*>(C + r1 * ldc + gc) = __floats2half2_rn(v2, v3);
            }
        }
    }
}

// ---------------------------------------------------------------------------
extern "C" void kernel_launch(void* const* d_in, const int* in_sizes, int n_in,
                              void* d_out, int out_size)
{
    const float* x    = (const float*)d_in[0];
    const float* nw   = (const float*)d_in[1];
    const float* rw   = (const float*)d_in[2];
    const float* rb   = (const float*)d_in[3];
    const float* qkv  = (const float*)d_in[4];
    const float* proj = (const float*)d_in[5];
    const float* pb   = (const float*)d_in[6];
    const float* ow   = (const float*)d_in[7];
    float* out = (float*)d_out;

    __half *xn, *v, *eo, *qvt, *pjt, *owt;
    float *rt;
    cudaGetSymbolAddress((void**)&xn,  g_xn);
    cudaGetSymbolAddress((void**)&v,   g_v);
    cudaGetSymbolAddress((void**)&eo,  g_eo);
    cudaGetSymbolAddress((void**)&rt,  g_rt);
    cudaGetSymbolAddress((void**)&qvt, g_qvt);
    cudaGetSymbolAddress((void**)&pjt, g_pjt);
    cudaGetSymbolAddress((void**)&owt, g_owt);

    cudaFuncSetAttribute(gemm_h<0>, cudaFuncAttributeMaxDynamicSharedMemorySize, G_SMEM);
    cudaFuncSetAttribute(gemm_h<1>, cudaFuncAttributeMaxDynamicSharedMemorySize, G_SMEM);
    cudaFuncSetAttribute(gemm_h<2>, cudaFuncAttributeMaxDynamicSharedMemorySize, G_SMEM);

    // 1) RMSNorm (writes fp16 xn), then router softmax from xn
    rmsnorm_kernel<<<BROWS, 256>>>(x, nw, xn);
    router_kernel<<<BROWS / 32, 256>>>(xn, rw, rb, rt);

    // 2) weight transposes (+ fp16 round)
    transpose_h<<<dim3(16, 16, 4), 256>>>(qkv, qvt, 3 * DEXP, 2 * DEXP, DEXP,
                                          (long long)DEXP * 3 * DEXP, (long long)DEXP * DEXP);
    transpose_h<<<dim3(16, 16, 4), 256>>>(proj, pjt, DEXP, 0, DEXP,
                                          (long long)DEXP * DEXP, (long long)DEXP * DEXP);
    transpose_h<<<dim3(64, 64, 1), 256>>>(ow, owt, DMODEL, 0, DMODEL, 0, 0);

    // 3) v = xs @ qkv_w[:,:,2dE:]   per expert: M=32768, N=512, K=512
    gemm_h<0><<<dim3(2, 256, 4), 256, G_SMEM>>>(
        xn, DMODEL, DEXP, qvt, DEXP, (long long)DEXP * DEXP,
        v, DMODEL, DEXP, DEXP, nullptr, nullptr, nullptr);

    // 4) eo = (v @ proj + pb) * routing
    gemm_h<1><<<dim3(2, 256, 4), 256, G_SMEM>>>(
        v, DMODEL, DEXP, pjt, DEXP, (long long)DEXP * DEXP,
        eo, DMODEL, DEXP, DEXP, pb, rt, nullptr);

    // 5) out = x + eo @ out_w       M=32768, N=2048, K=2048
    gemm_h<2><<<dim3(8, 256, 1), 256, G_SMEM>>>(
        eo, DMODEL, 0, owt, DMODEL, 0,
        out, DMODEL, 0, DMODEL, nullptr, nullptr, x);
}